// round 5
// baseline (speedup 1.0000x reference)
#include <cuda_runtime.h>

#define B_  16
#define C_  256
#define H_  64
#define W_  64
#define K_  31
#define PAD_ 15
#define HW_ 4096

// dwconv: vertical-pair packed tile
#define PV_ROWS 62          // r = 0..61 ; pair (tile r, tile r+32)
#define PV_COLS 94          // 64 + 30 halo
#define PV_S    95          // f2 row stride (odd -> conflict-free LDS.64 across rows)
#define WROW    31          // weight row (f2 per kh) -- broadcast loads, no pad needed
#define DW_SMEM_BYTES ((PV_ROWS * PV_S + K_ * WROW) * 8)

// Scratch (allocation-free rule: __device__ globals)
__device__ float g_y[(size_t)B_ * C_ * HW_];
__device__ float g_psum[C_ * B_];
__device__ float g_psumsq[C_ * B_];
__device__ float g_scale[C_];
__device__ float g_bias[C_];

// Packed f32x2 FMA (Blackwell sm_103a; only reachable via PTX)
#define FMA2(d, a, b) \
    asm("fma.rn.f32x2 %0, %1, %2, %0;" : "+l"(d) : "l"(a), "l"(b))

union U2F { unsigned long long u; float2 f; };

// ---------------------------------------------------------------------------
// Kernel 1: depthwise 31x31 conv, vertical-pair FFMA2.
// 128 threads: lane = output row h (0..31, also h+32), tid>>5 = col group.
// 4 blocks/SM (16 warps) to hide LDS + FMA latency.
// ---------------------------------------------------------------------------
__global__ void __launch_bounds__(128, 4)
dwconv_kernel(const float* __restrict__ x, const float* __restrict__ dw) {
    extern __shared__ float2 sm[];
    float2* pv   = sm;                       // pv[r*95+c] = (tile(r,c), tile(r+32,c))
    float2* wsm2 = sm + PV_ROWS * PV_S;      // duplicated weights (w,w)
    __shared__ float red[2][4];

    const int bx  = blockIdx.x;
    const int c   = bx & (C_ - 1);
    const int b   = bx >> 8;
    const int tid = threadIdx.x;

    // weights for this channel, duplicated (w,w)
    const float* wp = dw + c * (K_ * K_);
    for (int i = tid; i < K_ * K_; i += 128) {
        float w = wp[i];
        wsm2[i] = make_float2(w, w);   // row kh at wsm2 + kh*31
    }

    // build vertical-pair tile straight from gmem (zero-padded halo)
    const float* xp = x + (size_t)(b * C_ + c) * HW_;
    for (int i = tid; i < PV_ROWS * PV_COLS; i += 128) {
        int r  = i / PV_COLS;
        int cc = i - r * PV_COLS;
        int gw = cc - PAD_;
        float v0 = 0.0f, v1 = 0.0f;
        if ((unsigned)gw < (unsigned)W_) {
            int gh0 = r - PAD_;           // tile row r
            int gh1 = r + 32 - PAD_;      // tile row r+32
            if ((unsigned)gh0 < (unsigned)H_) v0 = xp[gh0 * W_ + gw];
            if ((unsigned)gh1 < (unsigned)H_) v1 = xp[gh1 * W_ + gw];
        }
        pv[r * PV_S + cc] = make_float2(v0, v1);
    }
    __syncthreads();

    const int h  = tid & 31;          // output rows h and h+32
    const int w0 = (tid >> 5) << 4;   // 0,16,32,48

    unsigned long long acc2[16];      // acc2[j] = (out[h][w0+j], out[h+32][w0+j])
    #pragma unroll
    for (int j = 0; j < 16; ++j) acc2[j] = 0ULL;

    const unsigned long long* pvR =
        (const unsigned long long*)pv + (size_t)h * PV_S + w0;
    const unsigned long long* wR = (const unsigned long long*)wsm2;

    #pragma unroll 1
    for (int kh = 0; kh < K_; ++kh) {
        unsigned long long win[46];
        #pragma unroll
        for (int t = 0; t < 46; ++t) win[t] = pvR[t];
        #pragma unroll
        for (int kw = 0; kw < K_; ++kw) {
            const unsigned long long wpair = wR[kw];    // broadcast LDS.64
            #pragma unroll
            for (int j = 0; j < 16; ++j)
                FMA2(acc2[j], win[j + kw], wpair);
        }
        pvR += PV_S;
        wR  += WROW;
    }

    // unpack into two rows, store y, accumulate statistics
    float* ypA = g_y + (size_t)(b * C_ + c) * HW_ + h * W_ + w0;
    float* ypB = ypA + 32 * W_;
    float s = 0.0f, s2 = 0.0f;
    float rowA[16], rowB[16];
    #pragma unroll
    for (int j = 0; j < 16; ++j) {
        U2F u; u.u = acc2[j];
        rowA[j] = u.f.x;
        rowB[j] = u.f.y;
        s  += u.f.x + u.f.y;
        s2  = fmaf(u.f.x, u.f.x, s2);
        s2  = fmaf(u.f.y, u.f.y, s2);
    }
    #pragma unroll
    for (int q = 0; q < 4; ++q) {
        *(float4*)(ypA + 4 * q) = make_float4(rowA[4*q], rowA[4*q+1], rowA[4*q+2], rowA[4*q+3]);
        *(float4*)(ypB + 4 * q) = make_float4(rowB[4*q], rowB[4*q+1], rowB[4*q+2], rowB[4*q+3]);
    }
    #pragma unroll
    for (int off = 16; off > 0; off >>= 1) {
        s  += __shfl_down_sync(0xffffffffu, s,  off);
        s2 += __shfl_down_sync(0xffffffffu, s2, off);
    }
    const int warp = tid >> 5;
    const int lane = tid & 31;
    if (lane == 0) { red[0][warp] = s; red[1][warp] = s2; }
    __syncthreads();
    if (tid == 0) {
        float ts = 0.0f, t2 = 0.0f;
        #pragma unroll
        for (int w = 0; w < 4; ++w) { ts += red[0][w]; t2 += red[1][w]; }
        g_psum[c * B_ + b]   = ts;
        g_psumsq[c * B_ + b] = t2;
    }
}

// ---------------------------------------------------------------------------
// Kernel 2: fold B partials per channel -> scale/bias  (deterministic)
// ---------------------------------------------------------------------------
__global__ void stats_kernel(const float* __restrict__ gamma,
                             const float* __restrict__ beta) {
    const int c = threadIdx.x;
    float s = 0.0f, s2 = 0.0f;
    #pragma unroll
    for (int b = 0; b < B_; ++b) {
        s  += g_psum[c * B_ + b];
        s2 += g_psumsq[c * B_ + b];
    }
    const float inv  = 1.0f / (float)(B_ * HW_);
    const float mean = s * inv;
    const float var  = s2 * inv - mean * mean;
    const float rstd = rsqrtf(var + 1e-5f);
    const float sc   = rstd * gamma[c];
    g_scale[c] = sc;
    g_bias[c]  = beta[c] - mean * sc;
}

// ---------------------------------------------------------------------------
// Kernel 3: fused normalize+ReLU+pointwise GEMM (round-1 proven version)
// ---------------------------------------------------------------------------
__global__ __launch_bounds__(256) void pw_kernel(const float* __restrict__ pw,
                                                 float* __restrict__ out) {
    __shared__ float As[16][64];   // As[k][m] = pw[m0+m, c0+k]
    __shared__ float Bs[16][64];   // Bs[k][n] = relu(y*scale+bias)

    const int b   = blockIdx.z;
    const int m0  = blockIdx.y * 64;
    const int hw0 = blockIdx.x * 64;
    const int tid = threadIdx.x;
    const int tm  = tid >> 4;
    const int tn  = tid & 15;

    const int la_m  = tid >> 2;
    const int la_k4 = (tid & 3) * 4;
    const int lb_k  = tid >> 4;
    const int lb_n  = (tid & 15) * 4;

    const float* yb = g_y + (size_t)b * C_ * HW_ + hw0;

    float acc[4][4];
    #pragma unroll
    for (int i = 0; i < 4; ++i)
        #pragma unroll
        for (int j = 0; j < 4; ++j) acc[i][j] = 0.0f;

    for (int c0 = 0; c0 < C_; c0 += 16) {
        float4 a4 = *(const float4*)&pw[(m0 + la_m) * C_ + c0 + la_k4];
        As[la_k4 + 0][la_m] = a4.x;
        As[la_k4 + 1][la_m] = a4.y;
        As[la_k4 + 2][la_m] = a4.z;
        As[la_k4 + 3][la_m] = a4.w;
        {
            const int cc = c0 + lb_k;
            float4 b4 = *(const float4*)&yb[(size_t)cc * HW_ + lb_n];
            const float sc = g_scale[cc];
            const float bi = g_bias[cc];
            b4.x = fmaxf(fmaf(b4.x, sc, bi), 0.0f);
            b4.y = fmaxf(fmaf(b4.y, sc, bi), 0.0f);
            b4.z = fmaxf(fmaf(b4.z, sc, bi), 0.0f);
            b4.w = fmaxf(fmaf(b4.w, sc, bi), 0.0f);
            *(float4*)&Bs[lb_k][lb_n] = b4;
        }
        __syncthreads();

        #pragma unroll
        for (int kk = 0; kk < 16; ++kk) {
            const float4 av = *(const float4*)&As[kk][tm * 4];
            const float4 bv = *(const float4*)&Bs[kk][tn * 4];
            const float a_[4] = {av.x, av.y, av.z, av.w};
            const float b_[4] = {bv.x, bv.y, bv.z, bv.w};
            #pragma unroll
            for (int i = 0; i < 4; ++i)
                #pragma unroll
                for (int j = 0; j < 4; ++j)
                    acc[i][j] = fmaf(a_[i], b_[j], acc[i][j]);
        }
        __syncthreads();
    }

    #pragma unroll
    for (int i = 0; i < 4; ++i) {
        const int o = m0 + tm * 4 + i;
        float4 ov;
        ov.x = acc[i][0]; ov.y = acc[i][1]; ov.z = acc[i][2]; ov.w = acc[i][3];
        *(float4*)&out[(size_t)(b * C_ + o) * HW_ + hw0 + tn * 4] = ov;
    }
}

// ---------------------------------------------------------------------------
extern "C" void kernel_launch(void* const* d_in, const int* in_sizes, int n_in,
                              void* d_out, int out_size) {
    const float* x     = (const float*)d_in[0];  // (16,256,64,64)
    const float* dw    = (const float*)d_in[1];  // (256,1,31,31)
    const float* gamma = (const float*)d_in[2];  // (256,)
    const float* beta  = (const float*)d_in[3];  // (256,)
    const float* pw    = (const float*)d_in[4];  // (256,256)
    float* out = (float*)d_out;                  // (16,256,64,64)

    cudaFuncSetAttribute(dwconv_kernel,
                         cudaFuncAttributeMaxDynamicSharedMemorySize,
                         DW_SMEM_BYTES);

    dwconv_kernel<<<B_ * C_, 128, DW_SMEM_BYTES>>>(x, dw);
    stats_kernel<<<1, C_>>>(gamma, beta);
    pw_kernel<<<dim3(HW_ / 64, C_ / 64, B_), 256>>>(pw, out);
}